// round 1
// baseline (speedup 1.0000x reference)
#include <cuda_runtime.h>
#include <mma.h>
#include <cstdint>

using namespace nvcuda;

#define T_TOK 4096
#define DDIM  768
#define IDIM  2048
#define NEXP  8
#define TM    128
#define NTILES 40            // 4096/128 + 8 (worst-case per-expert padding)
#define PADROWS (NTILES*TM)  // 5120
#define KC    32
#define LDS   36             // smem leading dim (floats), 144B = 9*16B -> wmma-legal, conflict-poor

// Scratch (device globals: no allocation allowed)
__device__ int   g_perm[PADROWS];        // padded-row -> token (-1 = pad)
__device__ int   g_tile_expert[NTILES];  // tile -> expert (-1 = unused tile)
__device__ float g_h[(size_t)PADROWS * IDIM]; // silu(g)*u activations, fp32

// ---------------------------------------------------------------------------
// Routing: counting sort of tokens into 128-row-aligned expert groups.
// Handles position_index being int64 OR int32 (runtime detection).
// ---------------------------------------------------------------------------
__global__ void route_kernel(const void* __restrict__ pos) {
    __shared__ int cnt[NEXP], off[NEXP], cur[NEXP];
    __shared__ int s_not64;
    const int tid = threadIdx.x;
    if (tid < NEXP) { cnt[tid] = 0; cur[tid] = 0; }
    if (tid == 0) s_not64 = 0;
    __syncthreads();

    // If data is int32, reading the buffer as u64 pairs two entries: high half
    // is nonzero for ~7/8 of tokens -> value > 7 with overwhelming probability.
    const unsigned long long* pl = (const unsigned long long*)pos;
    for (int i = tid; i < T_TOK / 2; i += blockDim.x)
        if (pl[i] > 7ULL) s_not64 = 1;
    __syncthreads();
    const int is64 = !s_not64;
    const long long* p64 = (const long long*)pos;
    const int*       p32 = (const int*)pos;

    for (int t = tid; t < T_TOK; t += blockDim.x) {
        int e = is64 ? (int)p64[t] : p32[t];
        atomicAdd(&cnt[e], 1);
    }
    for (int i = tid; i < PADROWS; i += blockDim.x) g_perm[i] = -1;
    __syncthreads();

    if (tid == 0) {
        int o = 0;
        for (int e = 0; e < NEXP; e++) {
            off[e] = o;
            int nt = (cnt[e] + TM - 1) / TM;
            for (int k = 0; k < nt; k++) g_tile_expert[o / TM + k] = e;
            o += nt * TM;
        }
        for (int tl = o / TM; tl < NTILES; tl++) g_tile_expert[tl] = -1;
    }
    __syncthreads();

    for (int t = tid; t < T_TOK; t += blockDim.x) {
        int e = is64 ? (int)p64[t] : p32[t];
        int p = off[e] + atomicAdd(&cur[e], 1);
        g_perm[p] = t;  // order within group irrelevant: rows are independent
    }
}

// ---------------------------------------------------------------------------
// GEMM1: H[tile rows, n0:n0+64] = silu(X @ Gw[e]^T) * (X @ Uw[e]^T)
// tf32 WMMA, block tile 128x64, K-chunk 32, 8 warps (4x2), warp tile 32x32.
// ---------------------------------------------------------------------------
__global__ __launch_bounds__(256) void gemm1_kernel(
    const float* __restrict__ x,
    const float* __restrict__ gw,
    const float* __restrict__ uw) {
    const int tile = blockIdx.x;
    const int e = g_tile_expert[tile];
    if (e < 0) return;
    const int n0 = blockIdx.y * 64;

    __shared__ float As[128 * LDS];
    __shared__ float Bg[64 * LDS];
    __shared__ float Bu[64 * LDS];
    __shared__ int   rowtok[128];

    const int tid = threadIdx.x;
    if (tid < 128) rowtok[tid] = g_perm[tile * TM + tid];

    const float* gwe = gw + ((size_t)e * IDIM + n0) * DDIM;
    const float* uwe = uw + ((size_t)e * IDIM + n0) * DDIM;

    const int wid = tid >> 5, wm = wid >> 1, wn = wid & 1;

    wmma::fragment<wmma::accumulator, 16, 16, 8, float> aG[2][2], aU[2][2];
#pragma unroll
    for (int i = 0; i < 2; i++)
#pragma unroll
        for (int j = 0; j < 2; j++) {
            wmma::fill_fragment(aG[i][j], 0.0f);
            wmma::fill_fragment(aU[i][j], 0.0f);
        }
    __syncthreads();  // rowtok ready

    for (int k0 = 0; k0 < DDIM; k0 += KC) {
        // A tile: 128x32 = 1024 float4; 4 per thread
#pragma unroll
        for (int j = 0; j < 4; j++) {
            int pos = tid + 256 * j;
            int r = pos >> 3, c = pos & 7;
            int t = rowtok[r];
            float4 v = make_float4(0.f, 0.f, 0.f, 0.f);
            if (t >= 0) v = *(const float4*)(x + (size_t)t * DDIM + k0 + c * 4);
            float* d = &As[r * LDS + c * 4];
            d[0] = wmma::__float_to_tf32(v.x);
            d[1] = wmma::__float_to_tf32(v.y);
            d[2] = wmma::__float_to_tf32(v.z);
            d[3] = wmma::__float_to_tf32(v.w);
        }
        // B tiles: 64x32 each = 512 float4; 2 per thread per matrix
#pragma unroll
        for (int j = 0; j < 2; j++) {
            int pos = tid + 256 * j;
            int r = pos >> 3, c = pos & 7;
            float4 vg = *(const float4*)(gwe + (size_t)r * DDIM + k0 + c * 4);
            float4 vu = *(const float4*)(uwe + (size_t)r * DDIM + k0 + c * 4);
            float* dg = &Bg[r * LDS + c * 4];
            dg[0] = wmma::__float_to_tf32(vg.x);
            dg[1] = wmma::__float_to_tf32(vg.y);
            dg[2] = wmma::__float_to_tf32(vg.z);
            dg[3] = wmma::__float_to_tf32(vg.w);
            float* du = &Bu[r * LDS + c * 4];
            du[0] = wmma::__float_to_tf32(vu.x);
            du[1] = wmma::__float_to_tf32(vu.y);
            du[2] = wmma::__float_to_tf32(vu.z);
            du[3] = wmma::__float_to_tf32(vu.w);
        }
        __syncthreads();

#pragma unroll
        for (int ks = 0; ks < 4; ks++) {
            wmma::fragment<wmma::matrix_a, 16, 16, 8, wmma::precision::tf32, wmma::row_major> fa[2];
            wmma::fragment<wmma::matrix_b, 16, 16, 8, wmma::precision::tf32, wmma::col_major> fg[2], fu[2];
#pragma unroll
            for (int i = 0; i < 2; i++)
                wmma::load_matrix_sync(fa[i], &As[(wm * 32 + i * 16) * LDS + ks * 8], LDS);
#pragma unroll
            for (int j = 0; j < 2; j++) {
                wmma::load_matrix_sync(fg[j], &Bg[(wn * 32 + j * 16) * LDS + ks * 8], LDS);
                wmma::load_matrix_sync(fu[j], &Bu[(wn * 32 + j * 16) * LDS + ks * 8], LDS);
            }
#pragma unroll
            for (int i = 0; i < 2; i++)
#pragma unroll
                for (int j = 0; j < 2; j++) {
                    wmma::mma_sync(aG[i][j], fa[i], fg[j], aG[i][j]);
                    wmma::mma_sync(aU[i][j], fa[i], fu[j], aU[i][j]);
                }
        }
        __syncthreads();
    }

    // Fused epilogue: h = silu(g) * u, write fp32 scratch
#pragma unroll
    for (int i = 0; i < 2; i++)
#pragma unroll
        for (int j = 0; j < 2; j++) {
#pragma unroll
            for (int el = 0; el < aG[i][j].num_elements; el++) {
                float g = aG[i][j].x[el];
                float u = aU[i][j].x[el];
                aG[i][j].x[el] = (g / (1.0f + __expf(-g))) * u;
            }
            size_t row = (size_t)(tile * TM + wm * 32 + i * 16);
            wmma::store_matrix_sync(&g_h[row * IDIM + n0 + wn * 32 + j * 16],
                                    aG[i][j], IDIM, wmma::mem_row_major);
        }
}

// ---------------------------------------------------------------------------
// GEMM2: Out[token, n0:n0+64] = H @ Dw[e]^T, scatter rows via perm.
// ---------------------------------------------------------------------------
__global__ __launch_bounds__(256) void gemm2_kernel(
    const float* __restrict__ dw,
    float* __restrict__ out) {
    const int tile = blockIdx.x;
    const int e = g_tile_expert[tile];
    if (e < 0) return;
    const int n0 = blockIdx.y * 64;

    __shared__ float sh[128 * 68];  // K-loop: As(128*36)+Bd(64*36)=6912 fl; epilogue stage: 128*68=8704 fl
    float* As = sh;
    float* Bd = sh + 128 * LDS;
    __shared__ int rowtok[128];

    const int tid = threadIdx.x;
    if (tid < 128) rowtok[tid] = g_perm[tile * TM + tid];

    const float* dwe = dw + ((size_t)e * DDIM + n0) * IDIM;
    const int wid = tid >> 5, wm = wid >> 1, wn = wid & 1;

    wmma::fragment<wmma::accumulator, 16, 16, 8, float> acc[2][2];
#pragma unroll
    for (int i = 0; i < 2; i++)
#pragma unroll
        for (int j = 0; j < 2; j++) wmma::fill_fragment(acc[i][j], 0.0f);
    __syncthreads();

    for (int k0 = 0; k0 < IDIM; k0 += KC) {
#pragma unroll
        for (int j = 0; j < 4; j++) {
            int pos = tid + 256 * j;
            int r = pos >> 3, c = pos & 7;
            float4 v = *(const float4*)(&g_h[(size_t)(tile * TM + r) * IDIM + k0 + c * 4]);
            float* d = &As[r * LDS + c * 4];
            d[0] = wmma::__float_to_tf32(v.x);
            d[1] = wmma::__float_to_tf32(v.y);
            d[2] = wmma::__float_to_tf32(v.z);
            d[3] = wmma::__float_to_tf32(v.w);
        }
#pragma unroll
        for (int j = 0; j < 2; j++) {
            int pos = tid + 256 * j;
            int r = pos >> 3, c = pos & 7;
            float4 v = *(const float4*)(dwe + (size_t)r * IDIM + k0 + c * 4);
            float* d = &Bd[r * LDS + c * 4];
            d[0] = wmma::__float_to_tf32(v.x);
            d[1] = wmma::__float_to_tf32(v.y);
            d[2] = wmma::__float_to_tf32(v.z);
            d[3] = wmma::__float_to_tf32(v.w);
        }
        __syncthreads();

#pragma unroll
        for (int ks = 0; ks < 4; ks++) {
            wmma::fragment<wmma::matrix_a, 16, 16, 8, wmma::precision::tf32, wmma::row_major> fa[2];
            wmma::fragment<wmma::matrix_b, 16, 16, 8, wmma::precision::tf32, wmma::col_major> fb[2];
#pragma unroll
            for (int i = 0; i < 2; i++)
                wmma::load_matrix_sync(fa[i], &As[(wm * 32 + i * 16) * LDS + ks * 8], LDS);
#pragma unroll
            for (int j = 0; j < 2; j++)
                wmma::load_matrix_sync(fb[j], &Bd[(wn * 32 + j * 16) * LDS + ks * 8], LDS);
#pragma unroll
            for (int i = 0; i < 2; i++)
#pragma unroll
                for (int j = 0; j < 2; j++)
                    wmma::mma_sync(acc[i][j], fa[i], fb[j], acc[i][j]);
        }
        __syncthreads();
    }

    // Stage in smem (aliases the K-loop tiles; all reads done), then scatter.
#pragma unroll
    for (int i = 0; i < 2; i++)
#pragma unroll
        for (int j = 0; j < 2; j++)
            wmma::store_matrix_sync(&sh[(wm * 32 + i * 16) * 68 + wn * 32 + j * 16],
                                    acc[i][j], 68, wmma::mem_row_major);
    __syncthreads();

#pragma unroll
    for (int j = 0; j < 8; j++) {
        int pos = tid + 256 * j;
        int r = pos >> 4, c = (pos & 15) * 4;
        int t = rowtok[r];
        if (t >= 0)
            *(float4*)(out + (size_t)t * DDIM + n0 + c) = *(float4*)&sh[r * 68 + c];
    }
}

// ---------------------------------------------------------------------------
extern "C" void kernel_launch(void* const* d_in, const int* in_sizes, int n_in,
                              void* d_out, int out_size) {
    const float* x   = (const float*)d_in[0];
    const void*  pos = d_in[1];
    // d_in[2] = behavior_index: unused (behavior_injection=False)
    const float* gw  = (const float*)d_in[3];
    const float* uw  = (const float*)d_in[4];
    const float* dw  = (const float*)d_in[5];
    float* out = (float*)d_out;

    route_kernel<<<1, 256>>>(pos);
    gemm1_kernel<<<dim3(NTILES, IDIM / 64), 256>>>(x, gw, uw);
    gemm2_kernel<<<dim3(NTILES, DDIM / 64), 256>>>(dw, out);
}

// round 2
// speedup vs baseline: 4.0765x; 4.0765x over previous
#include <cuda_runtime.h>
#include <cuda_fp16.h>
#include <mma.h>
#include <cstdint>

using namespace nvcuda;

#define T_TOK 4096
#define DDIM  768
#define IDIM  2048
#define NEXP  8
#define TM    128
#define NTILES 40            // 4096/128 + 8 (worst-case per-expert padding)
#define PADROWS (NTILES*TM)  // 5120
#define KC    64
#define LDH   72             // smem leading dim in halves (144B, 16B-multiple, conflict-poor)

// ---------------- device-global scratch (no allocation allowed) -------------
__device__ int    g_perm[PADROWS];
__device__ int    g_tile_expert[NTILES];
__device__ __half g_wg[(size_t)NEXP * IDIM * DDIM];   // 25 MB
__device__ __half g_wu[(size_t)NEXP * IDIM * DDIM];   // 25 MB
__device__ __half g_wd[(size_t)NEXP * DDIM * IDIM];   // 25 MB
__device__ __half g_x [(size_t)T_TOK * DDIM];         // 6 MB
__device__ __half g_h [(size_t)PADROWS * IDIM];       // 21 MB

// ---------------- cp.async helpers ------------------------------------------
__device__ __forceinline__ void cp16(void* smem, const void* gmem) {
    uint32_t s = (uint32_t)__cvta_generic_to_shared(smem);
    asm volatile("cp.async.cg.shared.global [%0], [%1], 16;" :: "r"(s), "l"(gmem));
}
#define CP_COMMIT() asm volatile("cp.async.commit_group;")
#define CP_WAIT1()  asm volatile("cp.async.wait_group 1;")
#define CP_WAIT0()  asm volatile("cp.async.wait_group 0;")

// ---------------------------------------------------------------------------
// fp32 -> fp16 conversion (grid-stride, float4 -> 4 halves)
// sel: 0=gate_w, 1=up_w, 2=down_w, 3=x
// ---------------------------------------------------------------------------
__global__ void cvt_kernel(const float4* __restrict__ in, int n4, int sel) {
    uint2* out = sel == 0 ? (uint2*)g_wg
               : sel == 1 ? (uint2*)g_wu
               : sel == 2 ? (uint2*)g_wd
                          : (uint2*)g_x;
    int i = blockIdx.x * blockDim.x + threadIdx.x;
    int stride = gridDim.x * blockDim.x;
    for (; i < n4; i += stride) {
        float4 v = in[i];
        __half2 a = __floats2half2_rn(v.x, v.y);
        __half2 b = __floats2half2_rn(v.z, v.w);
        uint2 o;
        o.x = *(uint32_t*)&a;
        o.y = *(uint32_t*)&b;
        out[i] = o;
    }
}

// ---------------------------------------------------------------------------
// Routing: counting sort into 128-row-aligned expert groups (int64/int32 safe)
// ---------------------------------------------------------------------------
__global__ void route_kernel(const void* __restrict__ pos) {
    __shared__ int cnt[NEXP], off[NEXP], cur[NEXP];
    __shared__ int s_not64;
    const int tid = threadIdx.x;
    if (tid < NEXP) { cnt[tid] = 0; cur[tid] = 0; }
    if (tid == 0) s_not64 = 0;
    __syncthreads();

    const unsigned long long* pl = (const unsigned long long*)pos;
    for (int i = tid; i < T_TOK / 2; i += blockDim.x)
        if (pl[i] > 7ULL) s_not64 = 1;
    __syncthreads();
    const int is64 = !s_not64;
    const long long* p64 = (const long long*)pos;
    const int*       p32 = (const int*)pos;

    for (int t = tid; t < T_TOK; t += blockDim.x) {
        int e = is64 ? (int)p64[t] : p32[t];
        atomicAdd(&cnt[e], 1);
    }
    for (int i = tid; i < PADROWS; i += blockDim.x) g_perm[i] = -1;
    __syncthreads();

    if (tid == 0) {
        int o = 0;
        for (int e = 0; e < NEXP; e++) {
            off[e] = o;
            int nt = (cnt[e] + TM - 1) / TM;
            for (int k = 0; k < nt; k++) g_tile_expert[o / TM + k] = e;
            o += nt * TM;
        }
        for (int tl = o / TM; tl < NTILES; tl++) g_tile_expert[tl] = -1;
    }
    __syncthreads();

    for (int t = tid; t < T_TOK; t += blockDim.x) {
        int e = is64 ? (int)p64[t] : p32[t];
        int p = off[e] + atomicAdd(&cur[e], 1);
        g_perm[p] = t;
    }
}

// ---------------------------------------------------------------------------
// GEMM1: H = silu(X @ Gw^T) * (X @ Uw^T), fp16 WMMA, cp.async double buffer.
// Block: 128 rows x 64 cols (of both G and U). 8 warps (4x2), warp tile 32x32.
// Stage (halves): A 128x72, Bg 64x72, Bu 64x72 = 18432; two stages = 73728 B.
// ---------------------------------------------------------------------------
#define G1_STAGE 18432
__global__ __launch_bounds__(256) void gemm1_kernel() {
    const int tile = blockIdx.x;
    const int e = g_tile_expert[tile];
    if (e < 0) return;
    const int n0 = blockIdx.y * 64;

    extern __shared__ __half sh[];
    __shared__ int rowtok[128];
    const int tid = threadIdx.x;
    if (tid < 128) rowtok[tid] = g_perm[tile * TM + tid];
    __syncthreads();

    const __half* wg_p = g_wg + ((size_t)e * IDIM + n0) * DDIM;
    const __half* wu_p = g_wu + ((size_t)e * IDIM + n0) * DDIM;

    auto load_stage = [&](int s, int k0) {
        __half* A  = sh + s * G1_STAGE;
        __half* Bg = A + 128 * LDH;
        __half* Bu = Bg + 64 * LDH;
#pragma unroll
        for (int j = 0; j < 4; j++) {
            int pos = tid + 256 * j;
            int r = pos >> 3, c = pos & 7;
            int t = rowtok[r]; if (t < 0) t = 0;   // pad rows: load anything valid
            cp16(A + r * LDH + c * 8, g_x + (size_t)t * DDIM + k0 + c * 8);
        }
#pragma unroll
        for (int j = 0; j < 2; j++) {
            int pos = tid + 256 * j;
            int r = pos >> 3, c = pos & 7;
            cp16(Bg + r * LDH + c * 8, wg_p + (size_t)r * DDIM + k0 + c * 8);
            cp16(Bu + r * LDH + c * 8, wu_p + (size_t)r * DDIM + k0 + c * 8);
        }
    };

    const int wid = tid >> 5, wm = wid >> 1, wn = wid & 1;

    wmma::fragment<wmma::accumulator, 16, 16, 16, float> aG[2][2], aU[2][2];
#pragma unroll
    for (int i = 0; i < 2; i++)
#pragma unroll
        for (int j = 0; j < 2; j++) {
            wmma::fill_fragment(aG[i][j], 0.0f);
            wmma::fill_fragment(aU[i][j], 0.0f);
        }

    load_stage(0, 0);  CP_COMMIT();
    load_stage(1, KC); CP_COMMIT();

    const int NK = DDIM / KC;  // 12
    for (int kc = 0; kc < NK; kc++) {
        if (kc + 1 < NK) CP_WAIT1(); else CP_WAIT0();
        __syncthreads();
        const int s = kc & 1;
        const __half* A  = sh + s * G1_STAGE;
        const __half* Bg = A + 128 * LDH;
        const __half* Bu = Bg + 64 * LDH;
#pragma unroll
        for (int ks = 0; ks < KC / 16; ks++) {
            wmma::fragment<wmma::matrix_a, 16, 16, 16, __half, wmma::row_major> fa[2];
            wmma::fragment<wmma::matrix_b, 16, 16, 16, __half, wmma::col_major> fg[2], fu[2];
#pragma unroll
            for (int i = 0; i < 2; i++)
                wmma::load_matrix_sync(fa[i], A + (wm * 32 + i * 16) * LDH + ks * 16, LDH);
#pragma unroll
            for (int j = 0; j < 2; j++) {
                wmma::load_matrix_sync(fg[j], Bg + (wn * 32 + j * 16) * LDH + ks * 16, LDH);
                wmma::load_matrix_sync(fu[j], Bu + (wn * 32 + j * 16) * LDH + ks * 16, LDH);
            }
#pragma unroll
            for (int i = 0; i < 2; i++)
#pragma unroll
                for (int j = 0; j < 2; j++) {
                    wmma::mma_sync(aG[i][j], fa[i], fg[j], aG[i][j]);
                    wmma::mma_sync(aU[i][j], fa[i], fu[j], aU[i][j]);
                }
        }
        __syncthreads();
        if (kc + 2 < NK) { load_stage(s, (kc + 2) * KC); CP_COMMIT(); }
    }

    // Fused silu(g)*u epilogue -> fp16 g_h via smem float staging (stride 72)
#pragma unroll
    for (int i = 0; i < 2; i++)
#pragma unroll
        for (int j = 0; j < 2; j++)
#pragma unroll
            for (int el = 0; el < aG[i][j].num_elements; el++) {
                float g = aG[i][j].x[el];
                float u = aU[i][j].x[el];
                aG[i][j].x[el] = (g / (1.0f + __expf(-g))) * u;
            }
    float* st = (float*)sh;
    __syncthreads();
#pragma unroll
    for (int i = 0; i < 2; i++)
#pragma unroll
        for (int j = 0; j < 2; j++)
            wmma::store_matrix_sync(st + (wm * 32 + i * 16) * 72 + wn * 32 + j * 16,
                                    aG[i][j], 72, wmma::mem_row_major);
    __syncthreads();
    const size_t rowbase = (size_t)tile * TM;
#pragma unroll
    for (int j = 0; j < 16; j++) {
        int pos = tid + 256 * j;                 // 0..4095
        int r = pos >> 5, c2 = pos & 31;
        float2 v = *(float2*)&st[r * 72 + c2 * 2];
        *(__half2*)(g_h + (rowbase + r) * IDIM + n0 + c2 * 2) = __floats2half2_rn(v.x, v.y);
    }
}

// ---------------------------------------------------------------------------
// GEMM2: Out = H @ Dw^T, scatter rows via perm. Same pipeline, 128x64 tile.
// Stage (halves): A 128x72, B 64x72 = 13824; two stages = 55296 B.
// ---------------------------------------------------------------------------
#define G2_STAGE 13824
__global__ __launch_bounds__(256) void gemm2_kernel(float* __restrict__ out) {
    const int tile = blockIdx.x;
    const int e = g_tile_expert[tile];
    if (e < 0) return;
    const int n0 = blockIdx.y * 64;

    extern __shared__ __half sh[];
    __shared__ int rowtok[128];
    const int tid = threadIdx.x;
    if (tid < 128) rowtok[tid] = g_perm[tile * TM + tid];
    __syncthreads();

    const __half* wd_p = g_wd + ((size_t)e * DDIM + n0) * IDIM;
    const __half* hbase = g_h + (size_t)tile * TM * IDIM;

    auto load_stage = [&](int s, int k0) {
        __half* A = sh + s * G2_STAGE;
        __half* B = A + 128 * LDH;
#pragma unroll
        for (int j = 0; j < 4; j++) {
            int pos = tid + 256 * j;
            int r = pos >> 3, c = pos & 7;
            cp16(A + r * LDH + c * 8, hbase + (size_t)r * IDIM + k0 + c * 8);
        }
#pragma unroll
        for (int j = 0; j < 2; j++) {
            int pos = tid + 256 * j;
            int r = pos >> 3, c = pos & 7;
            cp16(B + r * LDH + c * 8, wd_p + (size_t)r * IDIM + k0 + c * 8);
        }
    };

    const int wid = tid >> 5, wm = wid >> 1, wn = wid & 1;

    wmma::fragment<wmma::accumulator, 16, 16, 16, float> acc[2][2];
#pragma unroll
    for (int i = 0; i < 2; i++)
#pragma unroll
        for (int j = 0; j < 2; j++) wmma::fill_fragment(acc[i][j], 0.0f);

    load_stage(0, 0);  CP_COMMIT();
    load_stage(1, KC); CP_COMMIT();

    const int NK = IDIM / KC;  // 32
    for (int kc = 0; kc < NK; kc++) {
        if (kc + 1 < NK) CP_WAIT1(); else CP_WAIT0();
        __syncthreads();
        const int s = kc & 1;
        const __half* A = sh + s * G2_STAGE;
        const __half* B = A + 128 * LDH;
#pragma unroll
        for (int ks = 0; ks < KC / 16; ks++) {
            wmma::fragment<wmma::matrix_a, 16, 16, 16, __half, wmma::row_major> fa[2];
            wmma::fragment<wmma::matrix_b, 16, 16, 16, __half, wmma::col_major> fb[2];
#pragma unroll
            for (int i = 0; i < 2; i++)
                wmma::load_matrix_sync(fa[i], A + (wm * 32 + i * 16) * LDH + ks * 16, LDH);
#pragma unroll
            for (int j = 0; j < 2; j++)
                wmma::load_matrix_sync(fb[j], B + (wn * 32 + j * 16) * LDH + ks * 16, LDH);
#pragma unroll
            for (int i = 0; i < 2; i++)
#pragma unroll
                for (int j = 0; j < 2; j++)
                    wmma::mma_sync(acc[i][j], fa[i], fb[j], acc[i][j]);
        }
        __syncthreads();
        if (kc + 2 < NK) { load_stage(s, (kc + 2) * KC); CP_COMMIT(); }
    }

    // Stage fp32 result, scatter valid rows.
    float* st = (float*)sh;
    __syncthreads();
#pragma unroll
    for (int i = 0; i < 2; i++)
#pragma unroll
        for (int j = 0; j < 2; j++)
            wmma::store_matrix_sync(st + (wm * 32 + i * 16) * 72 + wn * 32 + j * 16,
                                    acc[i][j], 72, wmma::mem_row_major);
    __syncthreads();
#pragma unroll
    for (int j = 0; j < 8; j++) {
        int pos = tid + 256 * j;                 // 0..2047
        int r = pos >> 4, c4 = (pos & 15) * 4;
        int t = rowtok[r];
        if (t >= 0)
            *(float4*)(out + (size_t)t * DDIM + n0 + c4) = *(float4*)&st[r * 72 + c4];
    }
}

// ---------------------------------------------------------------------------
extern "C" void kernel_launch(void* const* d_in, const int* in_sizes, int n_in,
                              void* d_out, int out_size) {
    const float* x   = (const float*)d_in[0];
    const void*  pos = d_in[1];
    // d_in[2] = behavior_index: unused
    const float* gw  = (const float*)d_in[3];
    const float* uw  = (const float*)d_in[4];
    const float* dw  = (const float*)d_in[5];
    float* out = (float*)d_out;

    cudaFuncSetAttribute(gemm1_kernel, cudaFuncAttributeMaxDynamicSharedMemorySize, 2 * G1_STAGE * 2);
    cudaFuncSetAttribute(gemm2_kernel, cudaFuncAttributeMaxDynamicSharedMemorySize, 2 * G2_STAGE * 2);

    const int W4 = NEXP * IDIM * DDIM / 4;   // 3,145,728 float4s per weight
    const int X4 = T_TOK * DDIM / 4;         // 786,432
    cvt_kernel<<<1184, 256>>>((const float4*)gw, W4, 0);
    cvt_kernel<<<1184, 256>>>((const float4*)uw, W4, 1);
    cvt_kernel<<<1184, 256>>>((const float4*)dw, W4, 2);
    cvt_kernel<<<1184, 256>>>((const float4*)x,  X4, 3);
    route_kernel<<<1, 256>>>(pos);

    gemm1_kernel<<<dim3(NTILES, IDIM / 64), 256, 2 * G1_STAGE * 2>>>();
    gemm2_kernel<<<dim3(NTILES, DDIM / 64), 256, 2 * G2_STAGE * 2>>>(out);
}